// round 2
// baseline (speedup 1.0000x reference)
#include <cuda_runtime.h>

// Problem constants
constexpr int BB = 8;
constexpr int NN = 1024;
constexpr int CC = 768;
constexpr int HH = 12;
constexpr int DD = 64;
constexpr float QSCALE = 0.125f;   // HEAD_DIM^-0.5

// Scratch (allocation-free rule: __device__ globals)
__device__ float g_q[BB * HH * NN * DD];   // [B,H,N,D], pre-scaled
__device__ float g_k[BB * HH * NN * DD];   // [B,H,N,D]
__device__ float g_v[BB * HH * NN * DD];   // [B,H,N,D]
__device__ float g_ao[BB * NN * CC];       // attention output [B,N,C]

// ---------------------------------------------------------------------------
// Tiled fp32 GEMM: C[m,n] = sum_k A[m,k] * W[n,k]   (K = 768 for both uses)
// BM=BN=128, BK=16, 256 threads, 8x8 microtile per thread.
// MODE 0: A = x, W = w_qkv, scatter into g_q/g_k/g_v (scale q)
// MODE 1: A = g_ao, W = w_proj, add bias, write d_out
// ---------------------------------------------------------------------------
template <int MODE>
__global__ __launch_bounds__(256) void gemm_kernel(
    const float* __restrict__ A, const float* __restrict__ W,
    const float* __restrict__ bias, float* __restrict__ Cout)
{
    __shared__ float As[16][132];
    __shared__ float Bs[16][132];

    const float* Ap = (MODE == 0) ? A : (const float*)g_ao;

    const int tid = threadIdx.x;
    const int tx = tid & 15;
    const int ty = tid >> 4;
    const int row0 = blockIdx.y * 128;
    const int col0 = blockIdx.x * 128;
    const int lr = tid >> 2;          // 0..63
    const int lc = (tid & 3) << 2;    // 0,4,8,12

    float acc[8][8];
#pragma unroll
    for (int i = 0; i < 8; ++i)
#pragma unroll
        for (int j = 0; j < 8; ++j) acc[i][j] = 0.f;

    for (int k0 = 0; k0 < 768; k0 += 16) {
        __syncthreads();
#pragma unroll
        for (int hh = 0; hh < 2; ++hh) {
            const int r = lr + hh * 64;
            float4 av = *(const float4*)(Ap + (size_t)(row0 + r) * 768 + k0 + lc);
            As[lc + 0][r] = av.x; As[lc + 1][r] = av.y;
            As[lc + 2][r] = av.z; As[lc + 3][r] = av.w;
            float4 bv = *(const float4*)(W + (size_t)(col0 + r) * 768 + k0 + lc);
            Bs[lc + 0][r] = bv.x; Bs[lc + 1][r] = bv.y;
            Bs[lc + 2][r] = bv.z; Bs[lc + 3][r] = bv.w;
        }
        __syncthreads();
#pragma unroll
        for (int kk = 0; kk < 16; ++kk) {
            float af[8], bf[8];
            *(float4*)&af[0] = *(const float4*)&As[kk][ty * 8];
            *(float4*)&af[4] = *(const float4*)&As[kk][ty * 8 + 4];
            *(float4*)&bf[0] = *(const float4*)&Bs[kk][tx * 8];
            *(float4*)&bf[4] = *(const float4*)&Bs[kk][tx * 8 + 4];
#pragma unroll
            for (int i = 0; i < 8; ++i)
#pragma unroll
                for (int j = 0; j < 8; ++j)
                    acc[i][j] += af[i] * bf[j];
        }
    }

    if (MODE == 0) {
        // columns of one block lie within a single s (qkv split): 768 % 128 == 0
        const int s = col0 / 768;
        float* dst = (s == 0) ? g_q : (s == 1) ? g_k : g_v;
        const float mul = (s == 0) ? QSCALE : 1.0f;
#pragma unroll
        for (int i = 0; i < 8; ++i) {
            const int bn = row0 + ty * 8 + i;
            const int b = bn >> 10, n = bn & 1023;
#pragma unroll
            for (int j = 0; j < 8; ++j) {
                const int o = col0 - s * 768 + tx * 8 + j;  // 0..767
                const int h = o >> 6, d = o & 63;
                dst[(((size_t)b * HH + h) * NN + n) * DD + d] = acc[i][j] * mul;
            }
        }
    } else {
#pragma unroll
        for (int i = 0; i < 8; ++i) {
            const int bn = row0 + ty * 8 + i;
#pragma unroll
            for (int j = 0; j < 8; ++j) {
                const int o = col0 + tx * 8 + j;
                Cout[(size_t)bn * 768 + o] = acc[i][j] + bias[o];
            }
        }
    }
}

// ---------------------------------------------------------------------------
// Flash attention, fp32. Block = 128 query rows of one (b,h); 128 threads,
// one thread per query row. 16 K/V tiles of 64 keys each.
// Scores live in padded SMEM (stride 65 -> conflict-free per-thread rows).
// K/V SMEM reads are warp-uniform -> broadcast (cheap LDS).
// ---------------------------------------------------------------------------
constexpr int ATTN_SMEM_FLOATS = 64 * 64 * 2 + 128 * 65;  // Ks + Vs + Ss
constexpr int ATTN_SMEM_BYTES = ATTN_SMEM_FLOATS * 4;     // 66048

__global__ __launch_bounds__(128) void attn_kernel()
{
    extern __shared__ float smem[];
    float* Ks = smem;                 // [64][64]
    float* Vs = smem + 4096;          // [64][64]
    float* Ss = smem + 8192;          // [128][65]

    const int tid = threadIdx.x;
    const int h = blockIdx.y;
    const int b = blockIdx.z;
    const int n = blockIdx.x * 128 + tid;

    const float* qrow = g_q + (((size_t)b * HH + h) * NN + n) * DD;
    float q[64];
#pragma unroll
    for (int d = 0; d < 64; d += 4) {
        float4 v = *(const float4*)(qrow + d);
        q[d] = v.x; q[d + 1] = v.y; q[d + 2] = v.z; q[d + 3] = v.w;
    }
    float acc[64];
#pragma unroll
    for (int d = 0; d < 64; ++d) acc[d] = 0.f;
    float m = -1e30f, l = 0.f;

    const float* kb = g_k + ((size_t)b * HH + h) * NN * DD;
    const float* vb = g_v + ((size_t)b * HH + h) * NN * DD;
    float* srow = Ss + tid * 65;

    for (int t = 0; t < 16; ++t) {
        __syncthreads();
        // K/V tiles are contiguous 4096-float blocks -> fully coalesced copies
#pragma unroll
        for (int it = 0; it < 8; ++it) {
            const int f4 = it * 128 + tid;
            *(float4*)(Ks + f4 * 4) = *(const float4*)(kb + t * 4096 + f4 * 4);
            *(float4*)(Vs + f4 * 4) = *(const float4*)(vb + t * 4096 + f4 * 4);
        }
        __syncthreads();

        // QK^T for this thread's row against the 64-key tile
        float tmax = -1e30f;
#pragma unroll 2
        for (int j = 0; j < 64; ++j) {
            float s0 = 0.f, s1 = 0.f, s2 = 0.f, s3 = 0.f;
#pragma unroll
            for (int d = 0; d < 64; d += 4) {
                float4 kv = *(const float4*)(Ks + j * 64 + d);
                s0 += q[d] * kv.x;     s1 += q[d + 1] * kv.y;
                s2 += q[d + 2] * kv.z; s3 += q[d + 3] * kv.w;
            }
            const float s = (s0 + s1) + (s2 + s3);
            srow[j] = s;
            tmax = fmaxf(tmax, s);
        }

        // online softmax rescale
        const float mnew = fmaxf(m, tmax);
        const float alpha = __expf(m - mnew);
        l *= alpha;
#pragma unroll
        for (int d = 0; d < 64; ++d) acc[d] *= alpha;

        // P*V accumulation
#pragma unroll 2
        for (int j = 0; j < 64; ++j) {
            const float p = __expf(srow[j] - mnew);
            l += p;
#pragma unroll
            for (int d = 0; d < 64; d += 4) {
                float4 vv = *(const float4*)(Vs + j * 64 + d);
                acc[d]     += p * vv.x; acc[d + 1] += p * vv.y;
                acc[d + 2] += p * vv.z; acc[d + 3] += p * vv.w;
            }
        }
        m = mnew;
    }

    const float inv = 1.0f / l;
    float* orow = g_ao + ((size_t)b * NN + n) * CC + h * DD;
#pragma unroll
    for (int d = 0; d < 64; d += 4) {
        float4 o;
        o.x = acc[d] * inv;     o.y = acc[d + 1] * inv;
        o.z = acc[d + 2] * inv; o.w = acc[d + 3] * inv;
        *(float4*)(orow + d) = o;
    }
}

// ---------------------------------------------------------------------------
extern "C" void kernel_launch(void* const* d_in, const int* in_sizes, int n_in,
                              void* d_out, int out_size)
{
    const float* x      = (const float*)d_in[0];
    const float* w_qkv  = (const float*)d_in[1];
    const float* w_proj = (const float*)d_in[2];
    const float* b_proj = (const float*)d_in[3];
    float* out = (float*)d_out;

    // 66KB dynamic smem opt-in (idempotent, capture-safe host API)
    cudaFuncSetAttribute(attn_kernel,
                         cudaFuncAttributeMaxDynamicSharedMemorySize,
                         ATTN_SMEM_BYTES);

    // 1) QKV projection: M=8192, N=2304, K=768 -> scatter to g_q/g_k/g_v
    gemm_kernel<0><<<dim3(18, 64), 256>>>(x, w_qkv, nullptr, nullptr);

    // 2) Flash attention per (row-chunk, head, batch)
    attn_kernel<<<dim3(8, 12, 8), 128, ATTN_SMEM_BYTES>>>();

    // 3) Output projection: M=8192, N=768, K=768, + bias
    gemm_kernel<1><<<dim3(6, 64), 256>>>(nullptr, w_proj, b_proj, out);
}

// round 3
// speedup vs baseline: 2.9256x; 2.9256x over previous
#include <cuda_runtime.h>
#include <cstdint>

// Problem constants
constexpr int BB = 8;
constexpr int NN = 1024;
constexpr int CC = 768;
constexpr int HH = 12;
constexpr int DD = 64;
constexpr float QSCALE = 0.125f;   // HEAD_DIM^-0.5

// Scratch (allocation-free rule: __device__ globals)
__device__ float g_q[BB * HH * NN * DD];   // [B,H,N,D], pre-scaled
__device__ float g_k[BB * HH * NN * DD];   // [B,H,N,D]
__device__ float g_v[BB * HH * NN * DD];   // [B,H,N,D]
__device__ float g_ao[BB * NN * CC];       // attention output [B,N,C]

// ---------------------------------------------------------------------------
// TF32 helpers
// ---------------------------------------------------------------------------
__device__ __forceinline__ float f2tf(float x) {
    uint32_t u;
    asm("cvt.rna.tf32.f32 %0, %1;" : "=r"(u) : "f"(x));
    return __uint_as_float(u);
}

__device__ __forceinline__ void mma8(float c[4], const uint32_t a[4], const uint32_t b[2]) {
    asm volatile(
        "mma.sync.aligned.m16n8k8.row.col.f32.tf32.tf32.f32 "
        "{%0,%1,%2,%3},{%4,%5,%6,%7},{%8,%9},{%0,%1,%2,%3};\n"
        : "+f"(c[0]), "+f"(c[1]), "+f"(c[2]), "+f"(c[3])
        : "r"(a[0]), "r"(a[1]), "r"(a[2]), "r"(a[3]), "r"(b[0]), "r"(b[1]));
}

// ---------------------------------------------------------------------------
// TF32 tensor-core GEMM: C[m,n] = sum_k A[m,k] * W[n,k]   (K = 768)
// BM=BN=128, BK=32, 256 threads (8 warps, 4x2), warp tile 32x64.
// SMEM stride 36 floats (== 4 mod 32) -> all fragment LDS conflict-free.
// MODE 0: A = x, W = w_qkv, scatter into g_q/g_k/g_v (scale q)
// MODE 1: A = g_ao, W = w_proj, add bias, write d_out
// ---------------------------------------------------------------------------
template <int MODE>
__global__ __launch_bounds__(256) void gemm_tc(
    const float* __restrict__ A, const float* __restrict__ W,
    const float* __restrict__ bias, float* __restrict__ Cout)
{
    __shared__ float As[128 * 36];
    __shared__ float Bs[128 * 36];

    const float* Ap = (MODE == 0) ? A : (const float*)g_ao;

    const int tid  = threadIdx.x;
    const int lane = tid & 31;
    const int warp = tid >> 5;
    const int g  = lane >> 2;     // group id (row within fragment)
    const int tg = lane & 3;      // thread-in-group
    const int wm = warp >> 1;     // 0..3
    const int wn = warp & 1;      // 0..1
    const int row0 = blockIdx.y * 128;
    const int col0 = blockIdx.x * 128;
    const int sr = tid >> 1;            // staging row 0..127
    const int sc = (tid & 1) * 16;      // staging col 0 or 16

    float c[2][8][4];
#pragma unroll
    for (int mi = 0; mi < 2; ++mi)
#pragma unroll
        for (int ni = 0; ni < 8; ++ni)
#pragma unroll
            for (int r = 0; r < 4; ++r) c[mi][ni][r] = 0.f;

    for (int k0 = 0; k0 < 768; k0 += 32) {
        __syncthreads();
#pragma unroll
        for (int i = 0; i < 4; ++i) {
            const int cc0 = sc + i * 4;
            float4 av = *(const float4*)(Ap + (size_t)(row0 + sr) * 768 + k0 + cc0);
            *(float4*)(As + sr * 36 + cc0) =
                make_float4(f2tf(av.x), f2tf(av.y), f2tf(av.z), f2tf(av.w));
            float4 bv = *(const float4*)(W + (size_t)(col0 + sr) * 768 + k0 + cc0);
            *(float4*)(Bs + sr * 36 + cc0) =
                make_float4(f2tf(bv.x), f2tf(bv.y), f2tf(bv.z), f2tf(bv.w));
        }
        __syncthreads();

#pragma unroll
        for (int ks = 0; ks < 4; ++ks) {
            const int kk = ks * 8;
            uint32_t a[2][4];
#pragma unroll
            for (int mi = 0; mi < 2; ++mi) {
                const int base = (wm * 32 + mi * 16 + g) * 36 + kk + tg;
                a[mi][0] = __float_as_uint(As[base]);
                a[mi][1] = __float_as_uint(As[base + 8 * 36]);
                a[mi][2] = __float_as_uint(As[base + 4]);
                a[mi][3] = __float_as_uint(As[base + 8 * 36 + 4]);
            }
            uint32_t b[8][2];
#pragma unroll
            for (int ni = 0; ni < 8; ++ni) {
                const int bb = (wn * 64 + ni * 8 + g) * 36 + kk + tg;
                b[ni][0] = __float_as_uint(Bs[bb]);
                b[ni][1] = __float_as_uint(Bs[bb + 4]);
            }
#pragma unroll
            for (int mi = 0; mi < 2; ++mi)
#pragma unroll
                for (int ni = 0; ni < 8; ++ni)
                    mma8(c[mi][ni], a[mi], b[ni]);
        }
    }

    if (MODE == 0) {
        const int s = col0 / 768;                         // 0=q,1=k,2=v
        float* dst = (s == 0) ? g_q : (s == 1) ? g_k : g_v;
        const float mul = (s == 0) ? QSCALE : 1.0f;
        const int colr = col0 - s * 768;
#pragma unroll
        for (int mi = 0; mi < 2; ++mi) {
            const int r = row0 + wm * 32 + mi * 16 + g;
            const int b = r >> 10;
#pragma unroll
            for (int ni = 0; ni < 8; ++ni) {
                const int o = colr + wn * 64 + ni * 8 + 2 * tg;
                const int h = o >> 6, d = o & 63;
                const size_t base = (((size_t)b * HH + h) * NN);
                float2 v0 = make_float2(c[mi][ni][0] * mul, c[mi][ni][1] * mul);
                float2 v1 = make_float2(c[mi][ni][2] * mul, c[mi][ni][3] * mul);
                *(float2*)(dst + (base + (r & 1023)) * DD + d) = v0;
                *(float2*)(dst + (base + ((r + 8) & 1023)) * DD + d) = v1;
            }
        }
    } else {
#pragma unroll
        for (int mi = 0; mi < 2; ++mi) {
            const int r = row0 + wm * 32 + mi * 16 + g;
#pragma unroll
            for (int ni = 0; ni < 8; ++ni) {
                const int o = col0 + wn * 64 + ni * 8 + 2 * tg;
                float2 bb = *(const float2*)(bias + o);
                float2 v0 = make_float2(c[mi][ni][0] + bb.x, c[mi][ni][1] + bb.y);
                float2 v1 = make_float2(c[mi][ni][2] + bb.x, c[mi][ni][3] + bb.y);
                *(float2*)(Cout + (size_t)r * 768 + o) = v0;
                *(float2*)(Cout + (size_t)(r + 8) * 768 + o) = v1;
            }
        }
    }
}

// ---------------------------------------------------------------------------
// Flash attention with TF32 mma. Block = 64 query rows of one (b,h);
// 128 threads (4 warps, each owns 16 query rows). 16 K/V tiles of 64 keys.
// SMEM stride 68 (== 4 mod 32) -> conflict-free fragment LDS.
// Q fragments register-resident; P round-trips per-warp SMEM (tf32).
// ---------------------------------------------------------------------------
constexpr int ATT_LD = 68;
constexpr int ATT_SMEM_FLOATS = 2 * 64 * ATT_LD + 4 * 16 * ATT_LD;  // Ks+Vs+Ps
constexpr int ATT_SMEM_BYTES = ATT_SMEM_FLOATS * 4;                 // 52224

__global__ __launch_bounds__(128) void attn_tc()
{
    extern __shared__ float sm[];
    float* Ks = sm;
    float* Vs = sm + 64 * ATT_LD;
    const int tid  = threadIdx.x;
    const int lane = tid & 31;
    const int warp = tid >> 5;
    float* Ps = sm + 2 * 64 * ATT_LD + warp * 16 * ATT_LD;  // per-warp

    const int g  = lane >> 2;
    const int tg = lane & 3;
    const int h = blockIdx.y;
    const int b = blockIdx.z;
    const int q0 = blockIdx.x * 64;

    const size_t head = ((size_t)b * HH + h) * NN;
    const float* qb = g_q + (head + q0) * DD;
    const float* kb = g_k + head * DD;
    const float* vb = g_v + head * DD;

    // ---- stage Q into Ks region, then lift fragments to registers ----
#pragma unroll
    for (int i = 0; i < 8; ++i) {
        const int f4 = i * 128 + tid;
        const int row = f4 >> 4, c4 = (f4 & 15) * 4;
        float4 v = *(const float4*)(qb + row * 64 + c4);
        *(float4*)(Ks + row * ATT_LD + c4) =
            make_float4(f2tf(v.x), f2tf(v.y), f2tf(v.z), f2tf(v.w));
    }
    __syncthreads();
    uint32_t qf[8][4];
#pragma unroll
    for (int ks = 0; ks < 8; ++ks) {
        const int base = (warp * 16 + g) * ATT_LD + ks * 8 + tg;
        qf[ks][0] = __float_as_uint(Ks[base]);
        qf[ks][1] = __float_as_uint(Ks[base + 8 * ATT_LD]);
        qf[ks][2] = __float_as_uint(Ks[base + 4]);
        qf[ks][3] = __float_as_uint(Ks[base + 8 * ATT_LD + 4]);
    }

    float o[8][4];
#pragma unroll
    for (int ni = 0; ni < 8; ++ni)
#pragma unroll
        for (int r = 0; r < 4; ++r) o[ni][r] = 0.f;
    float m0r = -1e30f, m1r = -1e30f, l0 = 0.f, l1 = 0.f;

    for (int kt = 0; kt < 16; ++kt) {
        __syncthreads();   // protect Ks/Vs (and Q staging on first iter)
#pragma unroll
        for (int i = 0; i < 8; ++i) {
            const int f4 = i * 128 + tid;
            const int row = f4 >> 4, c4 = (f4 & 15) * 4;
            float4 kv = *(const float4*)(kb + (kt * 64 + row) * 64 + c4);
            *(float4*)(Ks + row * ATT_LD + c4) =
                make_float4(f2tf(kv.x), f2tf(kv.y), f2tf(kv.z), f2tf(kv.w));
            float4 vv = *(const float4*)(vb + (kt * 64 + row) * 64 + c4);
            *(float4*)(Vs + row * ATT_LD + c4) =
                make_float4(f2tf(vv.x), f2tf(vv.y), f2tf(vv.z), f2tf(vv.w));
        }
        __syncthreads();

        // ---- S = Q K^T (per warp: 16 rows x 64 keys) ----
        float s[8][4];
#pragma unroll
        for (int ni = 0; ni < 8; ++ni)
#pragma unroll
            for (int r = 0; r < 4; ++r) s[ni][r] = 0.f;
#pragma unroll
        for (int ks = 0; ks < 8; ++ks) {
#pragma unroll
            for (int ni = 0; ni < 8; ++ni) {
                uint32_t bfr[2];
                const int bb = (ni * 8 + g) * ATT_LD + ks * 8 + tg;
                bfr[0] = __float_as_uint(Ks[bb]);
                bfr[1] = __float_as_uint(Ks[bb + 4]);
                mma8(s[ni], qf[ks], bfr);
            }
        }

        // ---- online softmax ----
        float tm0 = -1e30f, tm1 = -1e30f;
#pragma unroll
        for (int ni = 0; ni < 8; ++ni) {
            tm0 = fmaxf(tm0, fmaxf(s[ni][0], s[ni][1]));
            tm1 = fmaxf(tm1, fmaxf(s[ni][2], s[ni][3]));
        }
#pragma unroll
        for (int off = 1; off <= 2; off <<= 1) {
            tm0 = fmaxf(tm0, __shfl_xor_sync(0xffffffffu, tm0, off));
            tm1 = fmaxf(tm1, __shfl_xor_sync(0xffffffffu, tm1, off));
        }
        const float mn0 = fmaxf(m0r, tm0);
        const float mn1 = fmaxf(m1r, tm1);
        const float al0 = __expf(m0r - mn0);
        const float al1 = __expf(m1r - mn1);
        l0 *= al0; l1 *= al1;
#pragma unroll
        for (int ni = 0; ni < 8; ++ni) {
            o[ni][0] *= al0; o[ni][1] *= al0;
            o[ni][2] *= al1; o[ni][3] *= al1;
        }
        float ls0 = 0.f, ls1 = 0.f;
#pragma unroll
        for (int ni = 0; ni < 8; ++ni) {
            const float p0 = __expf(s[ni][0] - mn0);
            const float p1 = __expf(s[ni][1] - mn0);
            const float p2 = __expf(s[ni][2] - mn1);
            const float p3 = __expf(s[ni][3] - mn1);
            ls0 += p0 + p1; ls1 += p2 + p3;
            *(float2*)(Ps + g * ATT_LD + ni * 8 + 2 * tg) =
                make_float2(f2tf(p0), f2tf(p1));
            *(float2*)(Ps + (g + 8) * ATT_LD + ni * 8 + 2 * tg) =
                make_float2(f2tf(p2), f2tf(p3));
        }
#pragma unroll
        for (int off = 1; off <= 2; off <<= 1) {
            ls0 += __shfl_xor_sync(0xffffffffu, ls0, off);
            ls1 += __shfl_xor_sync(0xffffffffu, ls1, off);
        }
        l0 += ls0; l1 += ls1;
        m0r = mn0; m1r = mn1;
        __syncwarp();

        // ---- O += P * V ----
#pragma unroll
        for (int ks = 0; ks < 8; ++ks) {
            uint32_t a[4];
            const int base = g * ATT_LD + ks * 8 + tg;
            a[0] = __float_as_uint(Ps[base]);
            a[1] = __float_as_uint(Ps[base + 8 * ATT_LD]);
            a[2] = __float_as_uint(Ps[base + 4]);
            a[3] = __float_as_uint(Ps[base + 8 * ATT_LD + 4]);
#pragma unroll
            for (int ni = 0; ni < 8; ++ni) {
                uint32_t bfr[2];
                const int bb = (ks * 8 + tg) * ATT_LD + ni * 8 + g;
                bfr[0] = __float_as_uint(Vs[bb]);
                bfr[1] = __float_as_uint(Vs[bb + 4 * ATT_LD]);
                mma8(o[ni], a, bfr);
            }
        }
        __syncwarp();
    }

    const float inv0 = 1.0f / l0;
    const float inv1 = 1.0f / l1;
    const int rA = q0 + warp * 16 + g;
    float* aoA = g_ao + ((size_t)b * NN + rA) * CC + h * DD;
    float* aoB = g_ao + ((size_t)b * NN + rA + 8) * CC + h * DD;
#pragma unroll
    for (int ni = 0; ni < 8; ++ni) {
        const int d = ni * 8 + 2 * tg;
        *(float2*)(aoA + d) = make_float2(o[ni][0] * inv0, o[ni][1] * inv0);
        *(float2*)(aoB + d) = make_float2(o[ni][2] * inv1, o[ni][3] * inv1);
    }
}

// ---------------------------------------------------------------------------
extern "C" void kernel_launch(void* const* d_in, const int* in_sizes, int n_in,
                              void* d_out, int out_size)
{
    const float* x      = (const float*)d_in[0];
    const float* w_qkv  = (const float*)d_in[1];
    const float* w_proj = (const float*)d_in[2];
    const float* b_proj = (const float*)d_in[3];
    float* out = (float*)d_out;

    cudaFuncSetAttribute(attn_tc,
                         cudaFuncAttributeMaxDynamicSharedMemorySize,
                         ATT_SMEM_BYTES);

    // 1) QKV projection: M=8192, N=2304, K=768 -> scatter to g_q/g_k/g_v
    gemm_tc<0><<<dim3(18, 64), 256>>>(x, w_qkv, nullptr, nullptr);

    // 2) Flash attention per (q-chunk, head, batch)
    attn_tc<<<dim3(16, 12, 8), 128, ATT_SMEM_BYTES>>>();

    // 3) Output projection: M=8192, N=768, K=768, + bias
    gemm_tc<1><<<dim3(6, 64), 256>>>(nullptr, w_proj, b_proj, out);
}

// round 5
// speedup vs baseline: 3.5662x; 1.2190x over previous
#include <cuda_runtime.h>
#include <cstdint>

// Problem constants
constexpr int BB = 8;
constexpr int NN = 1024;
constexpr int CC = 768;
constexpr int HH = 12;
constexpr int DD = 64;
constexpr float QSCALE = 0.125f;   // HEAD_DIM^-0.5

// Scratch (allocation-free rule: __device__ globals)
__device__ float g_q[BB * HH * NN * DD];   // [B,H,N,D], pre-scaled
__device__ float g_k[BB * HH * NN * DD];   // [B,H,N,D]
__device__ float g_v[BB * HH * NN * DD];   // [B,H,N,D]
__device__ float g_ao[BB * NN * CC];       // attention output [B,N,C]

// ---------------------------------------------------------------------------
// helpers (portable PTX only: sm_80-era features, no 'a'-suffix instructions)
// ---------------------------------------------------------------------------
__device__ __forceinline__ uint32_t smem_u32(const void* p) {
    uint32_t a;
    asm("{ .reg .u64 t; cvta.to.shared.u64 t, %1; cvt.u32.u64 %0, t; }" : "=r"(a) : "l"(p));
    return a;
}
__device__ __forceinline__ float f2tf(float x) {
    uint32_t u;
    asm("cvt.rna.tf32.f32 %0, %1;" : "=r"(u) : "f"(x));
    return __uint_as_float(u);
}
__device__ __forceinline__ uint32_t cvtu(float x) {
    uint32_t u;
    asm("cvt.rna.tf32.f32 %0, %1;" : "=r"(u) : "f"(x));
    return u;
}
__device__ __forceinline__ void mma8(float c[4], const uint32_t a[4], const uint32_t b[2]) {
    asm volatile(
        "mma.sync.aligned.m16n8k8.row.col.f32.tf32.tf32.f32 "
        "{%0,%1,%2,%3},{%4,%5,%6,%7},{%8,%9},{%0,%1,%2,%3};\n"
        : "+f"(c[0]), "+f"(c[1]), "+f"(c[2]), "+f"(c[3])
        : "r"(a[0]), "r"(a[1]), "r"(a[2]), "r"(a[3]), "r"(b[0]), "r"(b[1]));
}
__device__ __forceinline__ void cp16(uint32_t dst, const void* src) {
    asm volatile("cp.async.cg.shared.global [%0], [%1], 16;" :: "r"(dst), "l"(src));
}
__device__ __forceinline__ void cp_commit() {
    asm volatile("cp.async.commit_group;" ::: "memory");
}
template <int N> __device__ __forceinline__ void cp_wait_group() {
    asm volatile("cp.async.wait_group %0;" :: "n"(N) : "memory");
}

// ---------------------------------------------------------------------------
// TF32 tensor-core GEMM: C[m,n] = sum_k A[m,k] * W[n,k], K = 768.
// Block tile 128x128, 128 threads (4 warps, 2x2), warp tile 64x64.
// BK=32 slabs, cp.async double-buffered (raw fp32 in smem, cvt after LDS).
// SMEM row stride 36 floats (== 4 mod 32) -> fragment LDS conflict-free.
// MODE 0: A = x, W = w_qkv -> scatter g_q/g_k/g_v (q scaled)
// MODE 1: A = g_ao, W = w_proj -> d_out + bias
// ---------------------------------------------------------------------------
constexpr int GEMM_SMEM_BYTES = 4 * 128 * 36 * 4;   // A0,A1,B0,B1 = 73728

template <int MODE>
__global__ __launch_bounds__(128) void gemm_tc(
    const float* __restrict__ A, const float* __restrict__ W,
    const float* __restrict__ bias, float* __restrict__ Cout)
{
    extern __shared__ float smem[];
    float* Asb[2] = { smem,                smem + 128 * 36 };
    float* Bsb[2] = { smem + 2 * 128 * 36, smem + 3 * 128 * 36 };

    const float* Ap = (MODE == 0) ? A : (const float*)g_ao;

    const int tid  = threadIdx.x;
    const int lane = tid & 31;
    const int warp = tid >> 5;
    const int g  = lane >> 2;
    const int tg = lane & 3;
    const int wm = warp >> 1;    // 0..1
    const int wn = warp & 1;     // 0..1
    const int row0 = blockIdx.y * 128;
    const int col0 = blockIdx.x * 128;

    const uint32_t abase0 = smem_u32(Asb[0]);
    const uint32_t bbase0 = smem_u32(Bsb[0]);

    float c[4][8][4];
#pragma unroll
    for (int mi = 0; mi < 4; ++mi)
#pragma unroll
        for (int ni = 0; ni < 8; ++ni)
#pragma unroll
            for (int r = 0; r < 4; ++r) c[mi][ni][r] = 0.f;

    // slab loader: 2048 16B chunks (A rows then B rows), 16 per thread
    auto load_slab = [&](int slab, int buf) {
        const int k0 = slab * 32;
        const uint32_t ab = abase0 + buf * (128 * 36 * 4);
        const uint32_t bb = bbase0 + buf * (128 * 36 * 4);
#pragma unroll
        for (int j = 0; j < 16; ++j) {
            const int id = j * 128 + tid;
            const int isB = id >> 10;
            const int cid = id & 1023;
            const int row = cid >> 3;
            const int cc = cid & 7;
            const float* src = (isB ? W : Ap)
                + (size_t)((isB ? col0 : row0) + row) * 768 + k0 + cc * 4;
            const uint32_t dst = (isB ? bb : ab) + row * 144 + cc * 16;
            cp16(dst, src);
        }
        cp_commit();
    };

    load_slab(0, 0);

    for (int i = 0; i < 24; ++i) {
        const int cur = i & 1;
        if (i + 1 < 24) {
            load_slab(i + 1, cur ^ 1);
            cp_wait_group<1>();
        } else {
            cp_wait_group<0>();
        }
        __syncthreads();

        const float* as = Asb[cur];
        const float* bs = Bsb[cur];
#pragma unroll
        for (int ks = 0; ks < 4; ++ks) {
            const int kk = ks * 8;
            uint32_t a[4][4];
#pragma unroll
            for (int mi = 0; mi < 4; ++mi) {
                const int base = (wm * 64 + mi * 16 + g) * 36 + kk + tg;
                a[mi][0] = cvtu(as[base]);
                a[mi][1] = cvtu(as[base + 8 * 36]);
                a[mi][2] = cvtu(as[base + 4]);
                a[mi][3] = cvtu(as[base + 8 * 36 + 4]);
            }
            uint32_t b[8][2];
#pragma unroll
            for (int ni = 0; ni < 8; ++ni) {
                const int bb = (wn * 64 + ni * 8 + g) * 36 + kk + tg;
                b[ni][0] = cvtu(bs[bb]);
                b[ni][1] = cvtu(bs[bb + 4]);
            }
#pragma unroll
            for (int mi = 0; mi < 4; ++mi)
#pragma unroll
                for (int ni = 0; ni < 8; ++ni)
                    mma8(c[mi][ni], a[mi], b[ni]);
        }
        __syncthreads();
    }

    if (MODE == 0) {
        const int s = col0 / 768;                       // 0=q,1=k,2=v
        float* dstb = (s == 0) ? g_q : (s == 1) ? g_k : g_v;
        const float mul = (s == 0) ? QSCALE : 1.0f;
        const int colr = col0 - s * 768;
#pragma unroll
        for (int mi = 0; mi < 4; ++mi) {
            const int r = row0 + wm * 64 + mi * 16 + g;
            const int b = r >> 10;
#pragma unroll
            for (int ni = 0; ni < 8; ++ni) {
                const int o = colr + wn * 64 + ni * 8 + 2 * tg;
                const int h = o >> 6, d = o & 63;
                const size_t base = ((size_t)b * HH + h) * NN;
                *(float2*)(dstb + (base + (r & 1023)) * DD + d) =
                    make_float2(c[mi][ni][0] * mul, c[mi][ni][1] * mul);
                *(float2*)(dstb + (base + ((r + 8) & 1023)) * DD + d) =
                    make_float2(c[mi][ni][2] * mul, c[mi][ni][3] * mul);
            }
        }
    } else {
#pragma unroll
        for (int mi = 0; mi < 4; ++mi) {
            const int r = row0 + wm * 64 + mi * 16 + g;
#pragma unroll
            for (int ni = 0; ni < 8; ++ni) {
                const int o = col0 + wn * 64 + ni * 8 + 2 * tg;
                float2 bb = *(const float2*)(bias + o);
                *(float2*)(Cout + (size_t)r * 768 + o) =
                    make_float2(c[mi][ni][0] + bb.x, c[mi][ni][1] + bb.y);
                *(float2*)(Cout + (size_t)(r + 8) * 768 + o) =
                    make_float2(c[mi][ni][2] + bb.x, c[mi][ni][3] + bb.y);
            }
        }
    }
}

// ---------------------------------------------------------------------------
// Flash attention, TF32 mma. Block = 128 q-rows of one (b,h); 128 threads,
// 4 warps x 32 q-rows. 32 K/V tiles of 32 keys each.
// Q fragments loaded once from gmem into registers (no per-tile Q traffic).
// Ks/Vs stride 68, Ps stride 36 (both == 4 mod 32 -> conflict-free frags).
// ---------------------------------------------------------------------------
__global__ __launch_bounds__(128) void attn_tc()
{
    __shared__ float Ks[32 * 68];
    __shared__ float Vs[32 * 68];
    __shared__ float Ps[4 * 32 * 36];

    const int tid  = threadIdx.x;
    const int lane = tid & 31;
    const int warp = tid >> 5;
    const int g  = lane >> 2;
    const int tg = lane & 3;
    const int h = blockIdx.y;
    const int b = blockIdx.z;
    const int q0 = blockIdx.x * 128;

    const size_t head = ((size_t)b * HH + h) * NN;
    const float* qb = g_q + (head + q0 + warp * 32) * DD;
    const float* kb = g_k + head * DD;
    const float* vb = g_v + head * DD;
    float* Pw = Ps + warp * 32 * 36;

    // ---- Q fragments: direct gmem -> regs (one-time) ----
    uint32_t qf[8][8];
#pragma unroll
    for (int ks = 0; ks < 8; ++ks) {
        const int col = ks * 8 + tg;
#pragma unroll
        for (int mi = 0; mi < 2; ++mi) {
            const int row = mi * 16 + g;
            qf[ks][mi * 4 + 0] = cvtu(__ldg(qb + row * 64 + col));
            qf[ks][mi * 4 + 1] = cvtu(__ldg(qb + (row + 8) * 64 + col));
            qf[ks][mi * 4 + 2] = cvtu(__ldg(qb + row * 64 + col + 4));
            qf[ks][mi * 4 + 3] = cvtu(__ldg(qb + (row + 8) * 64 + col + 4));
        }
    }

    float o[2][8][4];
#pragma unroll
    for (int mi = 0; mi < 2; ++mi)
#pragma unroll
        for (int ni = 0; ni < 8; ++ni)
#pragma unroll
            for (int r = 0; r < 4; ++r) o[mi][ni][r] = 0.f;
    float mx[2][2] = { {-1e30f, -1e30f}, {-1e30f, -1e30f} };
    float lv[2][2] = { {0.f, 0.f}, {0.f, 0.f} };

    for (int kt = 0; kt < 32; ++kt) {
        __syncthreads();
        // stage K/V tile: 32 rows x 64 floats each, f2tf on the fly
#pragma unroll
        for (int it = 0; it < 8; ++it) {
            const int id = it * 128 + tid;
            const int isV = id >> 9;
            const int cid = id & 511;
            const int row = cid >> 4, c4 = (cid & 15) * 4;
            const float* src = (isV ? vb : kb) + (size_t)(kt * 32 + row) * 64 + c4;
            float4 v = *(const float4*)src;
            float* dst = (isV ? Vs : Ks) + row * 68 + c4;
            *(float4*)dst = make_float4(f2tf(v.x), f2tf(v.y), f2tf(v.z), f2tf(v.w));
        }
        __syncthreads();

        // ---- S = Q K^T (per warp: 32 rows x 32 keys) ----
        float s[2][4][4];
#pragma unroll
        for (int mi = 0; mi < 2; ++mi)
#pragma unroll
            for (int ni = 0; ni < 4; ++ni)
#pragma unroll
                for (int r = 0; r < 4; ++r) s[mi][ni][r] = 0.f;
#pragma unroll
        for (int ks = 0; ks < 8; ++ks) {
#pragma unroll
            for (int ni = 0; ni < 4; ++ni) {
                uint32_t bfr[2];
                const int bx = (ni * 8 + g) * 68 + ks * 8 + tg;
                bfr[0] = __float_as_uint(Ks[bx]);
                bfr[1] = __float_as_uint(Ks[bx + 4]);
                mma8(s[0][ni], &qf[ks][0], bfr);
                mma8(s[1][ni], &qf[ks][4], bfr);
            }
        }

        // ---- online softmax + P staging (per mi block of 16 rows) ----
#pragma unroll
        for (int mi = 0; mi < 2; ++mi) {
            float tm0 = -1e30f, tm1 = -1e30f;
#pragma unroll
            for (int ni = 0; ni < 4; ++ni) {
                tm0 = fmaxf(tm0, fmaxf(s[mi][ni][0], s[mi][ni][1]));
                tm1 = fmaxf(tm1, fmaxf(s[mi][ni][2], s[mi][ni][3]));
            }
#pragma unroll
            for (int off = 1; off <= 2; off <<= 1) {
                tm0 = fmaxf(tm0, __shfl_xor_sync(0xffffffffu, tm0, off));
                tm1 = fmaxf(tm1, __shfl_xor_sync(0xffffffffu, tm1, off));
            }
            const float mn0 = fmaxf(mx[mi][0], tm0);
            const float mn1 = fmaxf(mx[mi][1], tm1);
            const float al0 = __expf(mx[mi][0] - mn0);
            const float al1 = __expf(mx[mi][1] - mn1);
            lv[mi][0] *= al0; lv[mi][1] *= al1;
#pragma unroll
            for (int ni = 0; ni < 8; ++ni) {
                o[mi][ni][0] *= al0; o[mi][ni][1] *= al0;
                o[mi][ni][2] *= al1; o[mi][ni][3] *= al1;
            }
            float ls0 = 0.f, ls1 = 0.f;
#pragma unroll
            for (int ni = 0; ni < 4; ++ni) {
                const float p0 = __expf(s[mi][ni][0] - mn0);
                const float p1 = __expf(s[mi][ni][1] - mn0);
                const float p2 = __expf(s[mi][ni][2] - mn1);
                const float p3 = __expf(s[mi][ni][3] - mn1);
                ls0 += p0 + p1; ls1 += p2 + p3;
                *(float2*)(Pw + (mi * 16 + g) * 36 + ni * 8 + 2 * tg) =
                    make_float2(f2tf(p0), f2tf(p1));
                *(float2*)(Pw + (mi * 16 + g + 8) * 36 + ni * 8 + 2 * tg) =
                    make_float2(f2tf(p2), f2tf(p3));
            }
#pragma unroll
            for (int off = 1; off <= 2; off <<= 1) {
                ls0 += __shfl_xor_sync(0xffffffffu, ls0, off);
                ls1 += __shfl_xor_sync(0xffffffffu, ls1, off);
            }
            lv[mi][0] += ls0; lv[mi][1] += ls1;
            mx[mi][0] = mn0; mx[mi][1] = mn1;
        }
        __syncwarp();

        // ---- O += P * V ----
#pragma unroll
        for (int ks = 0; ks < 4; ++ks) {
            uint32_t a[2][4];
#pragma unroll
            for (int mi = 0; mi < 2; ++mi) {
                const int base = (mi * 16 + g) * 36 + ks * 8 + tg;
                a[mi][0] = __float_as_uint(Pw[base]);
                a[mi][1] = __float_as_uint(Pw[base + 8 * 36]);
                a[mi][2] = __float_as_uint(Pw[base + 4]);
                a[mi][3] = __float_as_uint(Pw[base + 8 * 36 + 4]);
            }
#pragma unroll
            for (int ni = 0; ni < 8; ++ni) {
                uint32_t bfr[2];
                const int bx = (ks * 8 + tg) * 68 + ni * 8 + g;
                bfr[0] = __float_as_uint(Vs[bx]);
                bfr[1] = __float_as_uint(Vs[bx + 4 * 68]);
                mma8(o[0][ni], a[0], bfr);
                mma8(o[1][ni], a[1], bfr);
            }
        }
        __syncwarp();
    }

    // ---- epilogue ----
#pragma unroll
    for (int mi = 0; mi < 2; ++mi) {
        const float inv0 = 1.0f / lv[mi][0];
        const float inv1 = 1.0f / lv[mi][1];
        const int rA = q0 + warp * 32 + mi * 16 + g;
        float* aoA = g_ao + ((size_t)b * NN + rA) * CC + h * DD;
        float* aoB = g_ao + ((size_t)b * NN + rA + 8) * CC + h * DD;
#pragma unroll
        for (int ni = 0; ni < 8; ++ni) {
            const int d = ni * 8 + 2 * tg;
            *(float2*)(aoA + d) = make_float2(o[mi][ni][0] * inv0, o[mi][ni][1] * inv0);
            *(float2*)(aoB + d) = make_float2(o[mi][ni][2] * inv1, o[mi][ni][3] * inv1);
        }
    }
}

// ---------------------------------------------------------------------------
extern "C" void kernel_launch(void* const* d_in, const int* in_sizes, int n_in,
                              void* d_out, int out_size)
{
    const float* x      = (const float*)d_in[0];
    const float* w_qkv  = (const float*)d_in[1];
    const float* w_proj = (const float*)d_in[2];
    const float* b_proj = (const float*)d_in[3];
    float* out = (float*)d_out;

    cudaFuncSetAttribute(gemm_tc<0>, cudaFuncAttributeMaxDynamicSharedMemorySize, GEMM_SMEM_BYTES);
    cudaFuncSetAttribute(gemm_tc<1>, cudaFuncAttributeMaxDynamicSharedMemorySize, GEMM_SMEM_BYTES);

    // 1) QKV projection: M=8192, N=2304, K=768 -> scatter to g_q/g_k/g_v
    gemm_tc<0><<<dim3(18, 64), 128, GEMM_SMEM_BYTES>>>(x, w_qkv, nullptr, nullptr);

    // 2) Flash attention per (q-chunk, head, batch)
    attn_tc<<<dim3(8, 12, 8), 128>>>();

    // 3) Output projection: M=8192, N=768, K=768, + bias
    gemm_tc<1><<<dim3(6, 64), 128, GEMM_SMEM_BYTES>>>(nullptr, w_proj, b_proj, out);
}

// round 6
// speedup vs baseline: 4.0176x; 1.1266x over previous
#include <cuda_runtime.h>
#include <cstdint>

// Problem constants
constexpr int BB = 8;
constexpr int NN = 1024;
constexpr int CC = 768;
constexpr int HH = 12;
constexpr int DD = 64;
constexpr float QSCALE = 0.125f;   // HEAD_DIM^-0.5 (exact power of two)

// Scratch (allocation-free rule: __device__ globals)
__device__ float g_q[BB * HH * NN * DD];   // tf32-rounded, pre-scaled
__device__ float g_k[BB * HH * NN * DD];   // tf32-rounded
__device__ float g_v[BB * HH * NN * DD];   // tf32-rounded
__device__ float g_ao[BB * NN * CC];       // tf32-rounded attention output
__device__ float g_xc[8192 * 768];         // tf32-rounded x
__device__ float g_wqc[2304 * 768];        // tf32-rounded w_qkv
__device__ float g_wpc[768 * 768];         // tf32-rounded w_proj

// ---------------------------------------------------------------------------
// helpers (portable PTX only — harness compiles at sm_103 (no 'a'))
// ---------------------------------------------------------------------------
__device__ __forceinline__ uint32_t smem_u32(const void* p) {
    uint32_t a;
    asm("{ .reg .u64 t; cvta.to.shared.u64 t, %1; cvt.u32.u64 %0, t; }" : "=r"(a) : "l"(p));
    return a;
}
__device__ __forceinline__ float f2tf(float x) {
    uint32_t u;
    asm("cvt.rna.tf32.f32 %0, %1;" : "=r"(u) : "f"(x));
    return __uint_as_float(u);
}
__device__ __forceinline__ void mma8(float c[4], const uint32_t a[4], const uint32_t b[2]) {
    asm volatile(
        "mma.sync.aligned.m16n8k8.row.col.f32.tf32.tf32.f32 "
        "{%0,%1,%2,%3},{%4,%5,%6,%7},{%8,%9},{%0,%1,%2,%3};\n"
        : "+f"(c[0]), "+f"(c[1]), "+f"(c[2]), "+f"(c[3])
        : "r"(a[0]), "r"(a[1]), "r"(a[2]), "r"(a[3]), "r"(b[0]), "r"(b[1]));
}
__device__ __forceinline__ void cp16(uint32_t dst, const void* src) {
    asm volatile("cp.async.cg.shared.global [%0], [%1], 16;" :: "r"(dst), "l"(src));
}
__device__ __forceinline__ void cp_commit() {
    asm volatile("cp.async.commit_group;" ::: "memory");
}
template <int N> __device__ __forceinline__ void cp_wait_group() {
    asm volatile("cp.async.wait_group %0;" :: "n"(N) : "memory");
}

// ---------------------------------------------------------------------------
// fp32 -> tf32-rounded fp32 (one-time pre-pass; removes cvt from inner loops)
// ---------------------------------------------------------------------------
__global__ __launch_bounds__(256) void cvt_tf32(
    const float4* __restrict__ src, float4* __restrict__ dst, int n4)
{
    const int i = blockIdx.x * 256 + threadIdx.x;
    if (i >= n4) return;
    float4 v = src[i];
    dst[i] = make_float4(f2tf(v.x), f2tf(v.y), f2tf(v.z), f2tf(v.w));
}

// ---------------------------------------------------------------------------
// TF32 tensor-core GEMM: C[m,n] = sum_k A[m,k] * W[n,k], K = 768.
// Block tile 128x128, 128 threads (4 warps 2x2), warp tile 64x64.
// BK=32 slabs, cp.async double-buffered; inputs pre-rounded to tf32 so the
// inner loop is pure LDS + MMA. Stride 36 floats -> conflict-free fragments.
// __launch_bounds__(128,3): <=170 regs, 3 CTAs/SM (216KB smem).
// MODE 0: A=g_xc, W=g_wqc -> scatter tf32-rounded g_q/g_k/g_v (q scaled)
// MODE 1: A=g_ao, W=g_wpc -> d_out + bias (fp32)
// ---------------------------------------------------------------------------
constexpr int GEMM_SMEM_BYTES = 4 * 128 * 36 * 4;   // A0,A1,B0,B1 = 73728

template <int MODE>
__global__ __launch_bounds__(128, 3) void gemm_tc(
    const float* __restrict__ bias, float* __restrict__ Cout)
{
    extern __shared__ float smem[];
    float* Asb[2] = { smem,                smem + 128 * 36 };
    float* Bsb[2] = { smem + 2 * 128 * 36, smem + 3 * 128 * 36 };

    const float* Ap = (MODE == 0) ? g_xc : g_ao;
    const float* W  = (MODE == 0) ? g_wqc : g_wpc;

    const int tid  = threadIdx.x;
    const int lane = tid & 31;
    const int warp = tid >> 5;
    const int g  = lane >> 2;
    const int tg = lane & 3;
    const int wm = warp >> 1;    // 0..1
    const int wn = warp & 1;     // 0..1
    const int row0 = blockIdx.y * 128;
    const int col0 = blockIdx.x * 128;

    const uint32_t abase0 = smem_u32(Asb[0]);
    const uint32_t bbase0 = smem_u32(Bsb[0]);

    float c[4][8][4];
#pragma unroll
    for (int mi = 0; mi < 4; ++mi)
#pragma unroll
        for (int ni = 0; ni < 8; ++ni)
#pragma unroll
            for (int r = 0; r < 4; ++r) c[mi][ni][r] = 0.f;

    auto load_slab = [&](int slab, int buf) {
        const int k0 = slab * 32;
        const uint32_t ab = abase0 + buf * (128 * 36 * 4);
        const uint32_t bb = bbase0 + buf * (128 * 36 * 4);
#pragma unroll
        for (int j = 0; j < 16; ++j) {
            const int id = j * 128 + tid;
            const int isB = id >> 10;
            const int cid = id & 1023;
            const int row = cid >> 3;
            const int cc = cid & 7;
            const float* src = (isB ? W : Ap)
                + (size_t)((isB ? col0 : row0) + row) * 768 + k0 + cc * 4;
            const uint32_t dst = (isB ? bb : ab) + row * 144 + cc * 16;
            cp16(dst, src);
        }
        cp_commit();
    };

    load_slab(0, 0);

    for (int i = 0; i < 24; ++i) {
        const int cur = i & 1;
        if (i + 1 < 24) {
            load_slab(i + 1, cur ^ 1);
            cp_wait_group<1>();
        } else {
            cp_wait_group<0>();
        }
        __syncthreads();

        const float* as = Asb[cur];
        const float* bs = Bsb[cur];
#pragma unroll
        for (int ks = 0; ks < 4; ++ks) {
            const int kk = ks * 8;
            uint32_t a[4][4];
#pragma unroll
            for (int mi = 0; mi < 4; ++mi) {
                const int base = (wm * 64 + mi * 16 + g) * 36 + kk + tg;
                a[mi][0] = __float_as_uint(as[base]);
                a[mi][1] = __float_as_uint(as[base + 8 * 36]);
                a[mi][2] = __float_as_uint(as[base + 4]);
                a[mi][3] = __float_as_uint(as[base + 8 * 36 + 4]);
            }
            uint32_t b[8][2];
#pragma unroll
            for (int ni = 0; ni < 8; ++ni) {
                const int bb = (wn * 64 + ni * 8 + g) * 36 + kk + tg;
                b[ni][0] = __float_as_uint(bs[bb]);
                b[ni][1] = __float_as_uint(bs[bb + 4]);
            }
#pragma unroll
            for (int mi = 0; mi < 4; ++mi)
#pragma unroll
                for (int ni = 0; ni < 8; ++ni)
                    mma8(c[mi][ni], a[mi], b[ni]);
        }
        __syncthreads();
    }

    if (MODE == 0) {
        const int s = col0 / 768;                       // 0=q,1=k,2=v
        float* dstb = (s == 0) ? g_q : (s == 1) ? g_k : g_v;
        const float mul = (s == 0) ? QSCALE : 1.0f;
        const int colr = col0 - s * 768;
#pragma unroll
        for (int mi = 0; mi < 4; ++mi) {
            const int r = row0 + wm * 64 + mi * 16 + g;
            const int b = r >> 10;
#pragma unroll
            for (int ni = 0; ni < 8; ++ni) {
                const int o = colr + wn * 64 + ni * 8 + 2 * tg;
                const int h = o >> 6, d = o & 63;
                const size_t base = ((size_t)b * HH + h) * NN;
                *(float2*)(dstb + (base + (r & 1023)) * DD + d) =
                    make_float2(f2tf(c[mi][ni][0] * mul), f2tf(c[mi][ni][1] * mul));
                *(float2*)(dstb + (base + ((r + 8) & 1023)) * DD + d) =
                    make_float2(f2tf(c[mi][ni][2] * mul), f2tf(c[mi][ni][3] * mul));
            }
        }
    } else {
#pragma unroll
        for (int mi = 0; mi < 4; ++mi) {
            const int r = row0 + wm * 64 + mi * 16 + g;
#pragma unroll
            for (int ni = 0; ni < 8; ++ni) {
                const int o = col0 + wn * 64 + ni * 8 + 2 * tg;
                float2 bb = *(const float2*)(bias + o);
                *(float2*)(Cout + (size_t)r * 768 + o) =
                    make_float2(c[mi][ni][0] + bb.x, c[mi][ni][1] + bb.y);
                *(float2*)(Cout + (size_t)(r + 8) * 768 + o) =
                    make_float2(c[mi][ni][2] + bb.x, c[mi][ni][3] + bb.y);
            }
        }
    }
}

// ---------------------------------------------------------------------------
// Flash attention, TF32 mma. Block = 128 q-rows of one (b,h); 128 threads,
// 4 warps x 32 q-rows. 16 K/V tiles of 64 keys, cp.async double-buffered.
// g_q/g_k/g_v already tf32-rounded -> staging is a raw copy, no cvt.
// Ks/Vs/Ps stride 68 floats (== 4 mod 32) -> conflict-free fragment LDS.
// ---------------------------------------------------------------------------
constexpr int KV_T = 64 * 68;                              // one K or V tile
constexpr int ATT_SMEM_FLOATS = 2 * 2 * KV_T + 4 * 32 * 68; // KV dbl + Ps
constexpr int ATT_SMEM_BYTES = ATT_SMEM_FLOATS * 4;         // 104448

__global__ __launch_bounds__(128) void attn_tc()
{
    extern __shared__ float sm[];
    const int tid  = threadIdx.x;
    const int lane = tid & 31;
    const int warp = tid >> 5;
    const int g  = lane >> 2;
    const int tg = lane & 3;
    const int h = blockIdx.y;
    const int b = blockIdx.z;
    const int q0 = blockIdx.x * 128;

    float* Pw = sm + 4 * KV_T + warp * 32 * 68;
    const uint32_t smbase = smem_u32(sm);

    const size_t head = ((size_t)b * HH + h) * NN;
    const float* qb = g_q + (head + q0 + warp * 32) * DD;
    const float* kb = g_k + head * DD;
    const float* vb = g_v + head * DD;

    // tile loader: K rows then V rows, 64 rows x 64 floats each; 16 cp16/thread
    auto load_tile = [&](int kt, int buf) {
#pragma unroll
        for (int j = 0; j < 16; ++j) {
            const int id = j * 128 + tid;
            const int isV = id >> 10;
            const int cid = id & 1023;
            const int row = cid >> 4;
            const int c4 = cid & 15;
            const float* src = (isV ? vb : kb) + (size_t)(kt * 64 + row) * 64 + c4 * 4;
            const uint32_t dst = smbase
                + (uint32_t)(buf * 2 * KV_T + isV * KV_T + row * 68) * 4 + c4 * 16;
            cp16(dst, src);
        }
        cp_commit();
    };

    load_tile(0, 0);

    // ---- Q fragments: direct gmem -> regs (one-time; data already tf32) ----
    uint32_t qf[8][8];
#pragma unroll
    for (int ks = 0; ks < 8; ++ks) {
        const int col = ks * 8 + tg;
#pragma unroll
        for (int mi = 0; mi < 2; ++mi) {
            const int row = mi * 16 + g;
            qf[ks][mi * 4 + 0] = __float_as_uint(__ldg(qb + row * 64 + col));
            qf[ks][mi * 4 + 1] = __float_as_uint(__ldg(qb + (row + 8) * 64 + col));
            qf[ks][mi * 4 + 2] = __float_as_uint(__ldg(qb + row * 64 + col + 4));
            qf[ks][mi * 4 + 3] = __float_as_uint(__ldg(qb + (row + 8) * 64 + col + 4));
        }
    }

    float o[2][8][4];
#pragma unroll
    for (int mi = 0; mi < 2; ++mi)
#pragma unroll
        for (int ni = 0; ni < 8; ++ni)
#pragma unroll
            for (int r = 0; r < 4; ++r) o[mi][ni][r] = 0.f;
    float mx[2][2] = { {-1e30f, -1e30f}, {-1e30f, -1e30f} };
    float lv[2][2] = { {0.f, 0.f}, {0.f, 0.f} };

    for (int kt = 0; kt < 16; ++kt) {
        const int cur = kt & 1;
        __syncthreads();                  // close compute kt-1 (read buf cur^1)
        if (kt + 1 < 16) {
            load_tile(kt + 1, cur ^ 1);
            cp_wait_group<1>();           // tile kt landed
        } else {
            cp_wait_group<0>();
        }
        __syncthreads();                  // tile kt visible to all warps

        const float* Ks = sm + cur * 2 * KV_T;
        const float* Vs = Ks + KV_T;

        // ---- S = Q K^T (per warp: 32 rows x 64 keys) ----
        float s[2][8][4];
#pragma unroll
        for (int mi = 0; mi < 2; ++mi)
#pragma unroll
            for (int ni = 0; ni < 8; ++ni)
#pragma unroll
                for (int r = 0; r < 4; ++r) s[mi][ni][r] = 0.f;
#pragma unroll
        for (int ks = 0; ks < 8; ++ks) {
#pragma unroll
            for (int ni = 0; ni < 8; ++ni) {
                uint32_t bfr[2];
                const int bx = (ni * 8 + g) * 68 + ks * 8 + tg;
                bfr[0] = __float_as_uint(Ks[bx]);
                bfr[1] = __float_as_uint(Ks[bx + 4]);
                mma8(s[0][ni], &qf[ks][0], bfr);
                mma8(s[1][ni], &qf[ks][4], bfr);
            }
        }

        // ---- online softmax + P staging ----
#pragma unroll
        for (int mi = 0; mi < 2; ++mi) {
            float tm0 = -1e30f, tm1 = -1e30f;
#pragma unroll
            for (int ni = 0; ni < 8; ++ni) {
                tm0 = fmaxf(tm0, fmaxf(s[mi][ni][0], s[mi][ni][1]));
                tm1 = fmaxf(tm1, fmaxf(s[mi][ni][2], s[mi][ni][3]));
            }
#pragma unroll
            for (int off = 1; off <= 2; off <<= 1) {
                tm0 = fmaxf(tm0, __shfl_xor_sync(0xffffffffu, tm0, off));
                tm1 = fmaxf(tm1, __shfl_xor_sync(0xffffffffu, tm1, off));
            }
            const float mn0 = fmaxf(mx[mi][0], tm0);
            const float mn1 = fmaxf(mx[mi][1], tm1);
            const float al0 = __expf(mx[mi][0] - mn0);
            const float al1 = __expf(mx[mi][1] - mn1);
            lv[mi][0] *= al0; lv[mi][1] *= al1;
#pragma unroll
            for (int ni = 0; ni < 8; ++ni) {
                o[mi][ni][0] *= al0; o[mi][ni][1] *= al0;
                o[mi][ni][2] *= al1; o[mi][ni][3] *= al1;
            }
            float ls0 = 0.f, ls1 = 0.f;
#pragma unroll
            for (int ni = 0; ni < 8; ++ni) {
                const float p0 = __expf(s[mi][ni][0] - mn0);
                const float p1 = __expf(s[mi][ni][1] - mn0);
                const float p2 = __expf(s[mi][ni][2] - mn1);
                const float p3 = __expf(s[mi][ni][3] - mn1);
                ls0 += p0 + p1; ls1 += p2 + p3;
                *(float2*)(Pw + (mi * 16 + g) * 68 + ni * 8 + 2 * tg) =
                    make_float2(f2tf(p0), f2tf(p1));
                *(float2*)(Pw + (mi * 16 + g + 8) * 68 + ni * 8 + 2 * tg) =
                    make_float2(f2tf(p2), f2tf(p3));
            }
#pragma unroll
            for (int off = 1; off <= 2; off <<= 1) {
                ls0 += __shfl_xor_sync(0xffffffffu, ls0, off);
                ls1 += __shfl_xor_sync(0xffffffffu, ls1, off);
            }
            lv[mi][0] += ls0; lv[mi][1] += ls1;
            mx[mi][0] = mn0; mx[mi][1] = mn1;
        }
        __syncwarp();

        // ---- O += P * V ----
#pragma unroll
        for (int ks = 0; ks < 8; ++ks) {
            uint32_t a[2][4];
#pragma unroll
            for (int mi = 0; mi < 2; ++mi) {
                const int base = (mi * 16 + g) * 68 + ks * 8 + tg;
                a[mi][0] = __float_as_uint(Pw[base]);
                a[mi][1] = __float_as_uint(Pw[base + 8 * 68]);
                a[mi][2] = __float_as_uint(Pw[base + 4]);
                a[mi][3] = __float_as_uint(Pw[base + 8 * 68 + 4]);
            }
#pragma unroll
            for (int ni = 0; ni < 8; ++ni) {
                uint32_t bfr[2];
                const int bx = (ks * 8 + tg) * 68 + ni * 8 + g;
                bfr[0] = __float_as_uint(Vs[bx]);
                bfr[1] = __float_as_uint(Vs[bx + 4 * 68]);
                mma8(o[0][ni], a[0], bfr);
                mma8(o[1][ni], a[1], bfr);
            }
        }
        __syncwarp();
    }

    // ---- epilogue: tf32-rounded g_ao (consumed by gemm1 without cvt) ----
#pragma unroll
    for (int mi = 0; mi < 2; ++mi) {
        const float inv0 = 1.0f / lv[mi][0];
        const float inv1 = 1.0f / lv[mi][1];
        const int rA = q0 + warp * 32 + mi * 16 + g;
        float* aoA = g_ao + ((size_t)b * NN + rA) * CC + h * DD;
        float* aoB = g_ao + ((size_t)b * NN + rA + 8) * CC + h * DD;
#pragma unroll
        for (int ni = 0; ni < 8; ++ni) {
            const int d = ni * 8 + 2 * tg;
            *(float2*)(aoA + d) =
                make_float2(f2tf(o[mi][ni][0] * inv0), f2tf(o[mi][ni][1] * inv0));
            *(float2*)(aoB + d) =
                make_float2(f2tf(o[mi][ni][2] * inv1), f2tf(o[mi][ni][3] * inv1));
        }
    }
}

// ---------------------------------------------------------------------------
extern "C" void kernel_launch(void* const* d_in, const int* in_sizes, int n_in,
                              void* d_out, int out_size)
{
    const float* x      = (const float*)d_in[0];
    const float* w_qkv  = (const float*)d_in[1];
    const float* w_proj = (const float*)d_in[2];
    const float* b_proj = (const float*)d_in[3];
    float* out = (float*)d_out;

    cudaFuncSetAttribute(gemm_tc<0>, cudaFuncAttributeMaxDynamicSharedMemorySize, GEMM_SMEM_BYTES);
    cudaFuncSetAttribute(gemm_tc<1>, cudaFuncAttributeMaxDynamicSharedMemorySize, GEMM_SMEM_BYTES);
    cudaFuncSetAttribute(attn_tc,   cudaFuncAttributeMaxDynamicSharedMemorySize, ATT_SMEM_BYTES);

    float *xc, *wqc, *wpc;
    cudaGetSymbolAddress((void**)&xc,  g_xc);
    cudaGetSymbolAddress((void**)&wqc, g_wqc);
    cudaGetSymbolAddress((void**)&wpc, g_wpc);

    // 0) one-time tf32 rounding of all GEMM operands
    cvt_tf32<<<(8192 * 768 / 4 + 255) / 256, 256>>>((const float4*)x,      (float4*)xc,  8192 * 768 / 4);
    cvt_tf32<<<(2304 * 768 / 4 + 255) / 256, 256>>>((const float4*)w_qkv,  (float4*)wqc, 2304 * 768 / 4);
    cvt_tf32<<<(768 * 768 / 4 + 255) / 256, 256>>>((const float4*)w_proj, (float4*)wpc, 768 * 768 / 4);

    // 1) QKV projection: M=8192, N=2304, K=768 -> scatter to g_q/g_k/g_v
    gemm_tc<0><<<dim3(18, 64), 128, GEMM_SMEM_BYTES>>>(nullptr, nullptr);

    // 2) Flash attention per (q-chunk, head, batch)
    attn_tc<<<dim3(8, 12, 8), 128, ATT_SMEM_BYTES>>>();

    // 3) Output projection: M=8192, N=768, K=768, + bias
    gemm_tc<1><<<dim3(6, 64), 128, GEMM_SMEM_BYTES>>>(b_proj, out);
}